// round 1
// baseline (speedup 1.0000x reference)
#include <cuda_runtime.h>
#include <math.h>

#define BATCH 64
#define NROW  307
#define NN    614
#define D     64

// Scratch (device globals — allocation-free per harness rules)
__device__ float g_Wh[(size_t)BATCH * NN * D];   // 10 MB
__device__ float g_Wh1[BATCH * NN];
__device__ float g_Wh2[BATCH * NN];
__device__ float g_cmax[BATCH * NN];
__device__ float g_cZinv[BATCH * NN];
__device__ int   g_row_idx[NN * NN];             // worst-case dense
__device__ int   g_row_cnt[NN];
__device__ int   g_col_idx[NN * NN];
__device__ int   g_col_cnt[NN];

// ---------------------------------------------------------------------------
// Kernel 0: build row-CSR and col-CSR of (adj > 0) via ballot compaction.
// Block = 64 threads: warp 0 handles row r, warp 1 handles column r.
// ---------------------------------------------------------------------------
__global__ void k_csr(const float* __restrict__ adj) {
    const int r    = blockIdx.x;
    const int lane = threadIdx.x & 31;
    const int warp = threadIdx.x >> 5;
    if (warp == 0) {
        int cnt = 0;
        for (int m0 = 0; m0 < NN; m0 += 32) {
            int m = m0 + lane;
            float v = (m < NN) ? adj[r * NN + m] : 0.f;
            unsigned msk = __ballot_sync(0xffffffffu, v > 0.f);
            if (v > 0.f) {
                int pos = cnt + __popc(msk & ((1u << lane) - 1u));
                g_row_idx[r * NN + pos] = m;
            }
            cnt += __popc(msk);
        }
        if (lane == 0) g_row_cnt[r] = cnt;
    } else {
        int cnt = 0;
        for (int n0 = 0; n0 < NN; n0 += 32) {
            int n = n0 + lane;
            float v = (n < NN) ? adj[n * NN + r] : 0.f;
            unsigned msk = __ballot_sync(0xffffffffu, v > 0.f);
            if (v > 0.f) {
                int pos = cnt + __popc(msk & ((1u << lane) - 1u));
                g_col_idx[r * NN + pos] = n;
            }
            cnt += __popc(msk);
        }
        if (lane == 0) g_col_cnt[r] = cnt;
    }
}

// ---------------------------------------------------------------------------
// Kernel 1: Wh = concat(ht, h) @ W  (rows 0..306 = ht, 307..613 = h),
// plus projections Wh1 = Wh @ a[:64], Wh2 = Wh @ a[64:].
// Block = 64 threads (one per output channel), 8 rows per block.
// ---------------------------------------------------------------------------
__global__ void k_wh(const float* __restrict__ h, const float* __restrict__ ht,
                     const float* __restrict__ W, const float* __restrict__ a) {
    const int b     = blockIdx.y;
    const int rbase = blockIdx.x * 8;
    const int tid   = threadIdx.x;   // 0..63 = output channel c

    __shared__ float xs[8 * 64];
    for (int k = tid; k < 8 * 64; k += 64) {
        int rl = k >> 6, i = k & 63;
        int gr = rbase + rl;
        float v = 0.f;
        if (gr < NN) {
            v = (gr < NROW) ? ht[((size_t)b * NROW + gr) * D + i]
                            : h [((size_t)b * NROW + (gr - NROW)) * D + i];
        }
        xs[k] = v;
    }
    __syncthreads();

    float acc[8];
#pragma unroll
    for (int r = 0; r < 8; r++) acc[r] = 0.f;
    const int c = tid;
#pragma unroll 4
    for (int i = 0; i < D; i++) {
        float w = W[i * D + c];
#pragma unroll
        for (int r = 0; r < 8; r++) acc[r] = fmaf(xs[r * 64 + i], w, acc[r]);
    }

    const float a1 = a[c], a2 = a[D + c];
    __shared__ float red1[2][8], red2[2][8];
    const int lane = tid & 31, wrp = tid >> 5;
#pragma unroll
    for (int r = 0; r < 8; r++) {
        int gr = rbase + r;
        if (gr < NN) g_Wh[((size_t)b * NN + gr) * D + c] = acc[r];
        float v1 = acc[r] * a1, v2 = acc[r] * a2;
#pragma unroll
        for (int off = 16; off > 0; off >>= 1) {
            v1 += __shfl_xor_sync(0xffffffffu, v1, off);
            v2 += __shfl_xor_sync(0xffffffffu, v2, off);
        }
        if (lane == 0) { red1[wrp][r] = v1; red2[wrp][r] = v2; }
    }
    __syncthreads();
    if (tid < 8) {
        int gr = rbase + tid;
        if (gr < NN) {
            g_Wh1[b * NN + gr] = red1[0][tid] + red1[1][tid];
            g_Wh2[b * NN + gr] = red2[0][tid] + red2[1][tid];
        }
    }
}

// ---------------------------------------------------------------------------
// Kernel 2: column-wise softmax statistics over axis=1 (online max/sum-exp),
// restricted to col-CSR nonzeros (masked entries contribute exactly 0).
// One thread per (b, column m).
// ---------------------------------------------------------------------------
__global__ void k_colstats() {
    const int b = blockIdx.y;
    const int m = blockIdx.x * blockDim.x + threadIdx.x;
    if (m >= NN) return;
    const int cnt = g_col_cnt[m];
    const float wh2m = g_Wh2[b * NN + m];
    const float* __restrict__ wh1 = &g_Wh1[b * NN];
    float mx = -INFINITY, Z = 0.f;
    for (int k = 0; k < cnt; k++) {
        int n   = g_col_idx[m * NN + k];
        float s = wh1[n] + wh2m;
        float e = (s > 0.f) ? s : 0.2f * s;   // LeakyReLU(0.2)
        if (e > mx) { Z = Z * __expf(mx - e) + 1.f; mx = e; }
        else        { Z += __expf(e - mx); }
    }
    g_cmax[b * NN + m]  = mx;
    g_cZinv[b * NN + m] = (cnt > 0) ? 1.f / Z : 0.f;
}

// ---------------------------------------------------------------------------
// Kernel 3: h_prime[b,n,:] = sum over row-CSR nonzeros m of
//   softmax_weight(n,m) * Wh[b,m,:]; then concat reorder + ELU.
// Block = 64 threads (one per channel), one (b, n) per block.
// ---------------------------------------------------------------------------
__global__ void k_out(float* __restrict__ out) {
    const int b    = blockIdx.y;
    const int nrow = blockIdx.x;
    const int c    = threadIdx.x;
    const float wh1n = g_Wh1[b * NN + nrow];
    const int cnt    = g_row_cnt[nrow];

    __shared__ float sw[64];
    __shared__ int   smi[64];
    float acc = 0.f;

    for (int k0 = 0; k0 < cnt; k0 += 64) {
        int k = k0 + c;
        float w = 0.f; int m = 0;
        if (k < cnt) {
            m = g_row_idx[nrow * NN + k];
            float s = wh1n + g_Wh2[b * NN + m];
            float e = (s > 0.f) ? s : 0.2f * s;
            w = __expf(e - g_cmax[b * NN + m]) * g_cZinv[b * NN + m];
        }
        sw[c] = w; smi[c] = m;
        __syncthreads();
        int lim = min(64, cnt - k0);
        for (int j = 0; j < lim; j++)
            acc = fmaf(sw[j], g_Wh[((size_t)b * NN + smi[j]) * D + c], acc);
        __syncthreads();
    }

    float r = (acc > 0.f) ? acc : expm1f(acc);   // ELU(alpha=1)
    size_t o;
    if (nrow < NROW) o = ((size_t)b * NROW + nrow) * 128 + c;
    else             o = ((size_t)b * NROW + (nrow - NROW)) * 128 + 64 + c;
    out[o] = r;
}

// ---------------------------------------------------------------------------
extern "C" void kernel_launch(void* const* d_in, const int* in_sizes, int n_in,
                              void* d_out, int out_size) {
    const float* h   = (const float*)d_in[0];
    const float* ht  = (const float*)d_in[1];
    const float* W   = (const float*)d_in[2];
    const float* a   = (const float*)d_in[3];
    const float* adj = (const float*)d_in[4];
    float* out = (float*)d_out;

    k_csr<<<NN, 64>>>(adj);
    k_wh<<<dim3((NN + 7) / 8, BATCH), 64>>>(h, ht, W, a);
    k_colstats<<<dim3((NN + 127) / 128, BATCH), 128>>>();
    k_out<<<dim3(NN, BATCH), 64>>>(out);
}